// round 8
// baseline (speedup 1.0000x reference)
#include <cuda_runtime.h>
#include <cuda_bf16.h>

#define N_NODES 1024
#define ROWPAD 36                     // floats per staged row (32 data + 4 pad)
#define SIN_FLOATS (4 * 128 * ROWPAD) // 4 staged rows x 128 j
#define EDGE_SMEM_BYTES ((SIN_FLOATS + 128) * 4)

typedef unsigned long long u64;

// ---------------- packed f32x2 helpers (sm_103a) ----------------
__device__ __forceinline__ u64 pack2(float lo, float hi) {
    u64 r; asm("mov.b64 %0, {%1, %2};" : "=l"(r) : "f"(lo), "f"(hi)); return r;
}
__device__ __forceinline__ void unpack2(u64 v, float& lo, float& hi) {
    asm("mov.b64 {%0, %1}, %2;" : "=f"(lo), "=f"(hi) : "l"(v));
}
__device__ __forceinline__ u64 ffma2(u64 a, u64 b, u64 c) {
    u64 d; asm("fma.rn.f32x2 %0, %1, %2, %3;" : "=l"(d) : "l"(a), "l"(b), "l"(c)); return d;
}

// ---------------- constant weights (uniform LDC only) ----------------
__constant__ float cWe1[96 * 16];
__constant__ float cbe2[16];
__constant__ float cWe2[16 * 16];
__constant__ float cWn1[48 * 32];
__constant__ float cbn1[32];
__constant__ float cWn2[32 * 32];
__constant__ float cbn2[32];

// ---------------- device scratch ----------------
__device__ __align__(16) float g_pa[N_NODES * 16];
__device__ __align__(16) float g_pb[N_NODES * 16];
__device__ __align__(16) float g_msga[N_NODES * 16];
__device__ __align__(16) float g_msgb[N_NODES * 16];

// ============ Kernel A: zero accumulators + per-node precompute (R5-proven) ============
__global__ __launch_bounds__(256) void prep_kernel(const float* __restrict__ na,
                                                   const float* __restrict__ nb,
                                                   const float* __restrict__ We1,
                                                   const float* __restrict__ be1) {
    __shared__ __align__(16) float sw[32 * 16];
    __shared__ __align__(16) float sb[16];

    const int b    = blockIdx.x;
    const bool isA = (b < 16);
    const int bb   = isA ? b : b - 16;
    const int tid  = threadIdx.x;

    reinterpret_cast<float2*>(sw)[tid] =
        reinterpret_cast<const float2*>(We1 + (isA ? 0 : 512))[tid];
    if (tid < 16) sb[tid] = isA ? be1[tid] : 0.0f;

    reinterpret_cast<float4*>((isA ? g_msga : g_msgb) + bb * 1024)[tid] =
        make_float4(0.f, 0.f, 0.f, 0.f);
    __syncthreads();

    const int node = bb * 64 + (tid >> 2);
    const int cg   = (tid & 3) * 4;

    const float* row = (isA ? na : nb) + node * 32;
    float x[32];
#pragma unroll
    for (int u = 0; u < 8; u++) {
        float4 v = reinterpret_cast<const float4*>(row)[u];
        x[u * 4 + 0] = v.x; x[u * 4 + 1] = v.y; x[u * 4 + 2] = v.z; x[u * 4 + 3] = v.w;
    }

    float4 acc = *reinterpret_cast<const float4*>(&sb[cg]);
#pragma unroll
    for (int k = 0; k < 32; k++) {
        const float xs = x[k];
        float4 w = *reinterpret_cast<const float4*>(&sw[k * 16 + cg]);
        acc.x = fmaf(xs, w.x, acc.x);
        acc.y = fmaf(xs, w.y, acc.y);
        acc.z = fmaf(xs, w.z, acc.z);
        acc.w = fmaf(xs, w.w, acc.w);
    }

    float* dst = (isA ? g_pa : g_pb) + node * 16 + cg;
    *reinterpret_cast<float4*>(dst) = acc;
}

// Butterfly channel-merging reduction: 16 channels x 32 lanes in 16 shfls.
__device__ __forceinline__ int chan16(int lane) {
    return ((lane & 1) ? 8 : 0) | ((lane & 2) ? 4 : 0) |
           ((lane & 4) ? 2 : 0) | ((lane & 8) ? 1 : 0);
}

__device__ __forceinline__ float warp_reduce16(float* v, int lane) {
    const unsigned FULL = 0xffffffffu;
    {
        bool hi = (lane & 1);
#pragma unroll
        for (int k = 0; k < 8; k++) {
            float send  = hi ? v[k] : v[k + 8];
            float other = __shfl_xor_sync(FULL, send, 1);
            v[k] = (hi ? v[k + 8] : v[k]) + other;
        }
    }
    {
        bool hi = (lane & 2);
#pragma unroll
        for (int k = 0; k < 4; k++) {
            float send  = hi ? v[k] : v[k + 4];
            float other = __shfl_xor_sync(FULL, send, 2);
            v[k] = (hi ? v[k + 4] : v[k]) + other;
        }
    }
    {
        bool hi = (lane & 4);
#pragma unroll
        for (int k = 0; k < 2; k++) {
            float send  = hi ? v[k] : v[k + 2];
            float other = __shfl_xor_sync(FULL, send, 4);
            v[k] = (hi ? v[k + 2] : v[k]) + other;
        }
    }
    {
        bool hi = (lane & 8);
        float send  = hi ? v[0] : v[1];
        float other = __shfl_xor_sync(FULL, send, 8);
        v[0] = (hi ? v[1] : v[0]) + other;
    }
    v[0] += __shfl_xor_sync(FULL, v[0], 16);
    return v[0];
}

// ============ Kernel B: edge MLP, 4-row weight reuse ============
// Block: 128 threads = 128 consecutive j; covers 8 i-rows in 2 iterations of 4.
// Each LDC.128 weight load feeds 4 rows in layer 1, 2 rows in layer 2:
// 512 LDC.128/thread vs R7's 1536.
__global__ __launch_bounds__(128) void edge_kernel(const float* __restrict__ edges,
                                                   float* __restrict__ out_e) {
    extern __shared__ __align__(16) float smem[];
    float* s_in = smem;                 // 4 * 128 * ROWPAD
    float* s_pa = smem + SIN_FLOATS;    // 128

    const int tid  = threadIdx.x;
    const int lane = tid & 31;
    const int j0   = blockIdx.x * 128;
    const int j    = j0 + tid;
    const int i0   = blockIdx.y * 8;

    s_pa[tid] = g_pa[i0 * 16 + tid];

    const u64* cWe1p = reinterpret_cast<const u64*>(cWe1);
    const u64* cWe2p = reinterpret_cast<const u64*>(cWe2);

    // pb[j] persistent (scalar floats; packed on the fly)
    float pb[16];
    {
        const float4* p4 = reinterpret_cast<const float4*>(g_pb + j * 16);
#pragma unroll
        for (int u = 0; u < 4; u++) {
            float4 v = p4[u];
            pb[u * 4 + 0] = v.x; pb[u * 4 + 1] = v.y;
            pb[u * 4 + 2] = v.z; pb[u * 4 + 3] = v.w;
        }
    }
    u64 be2p[8];
#pragma unroll
    for (int p = 0; p < 8; p++) be2p[p] = pack2(cbe2[2 * p], cbe2[2 * p + 1]);

    float msgb[16];
#pragma unroll
    for (int c = 0; c < 16; c++) msgb[c] = 0.0f;

#pragma unroll 1
    for (int it = 0; it < 2; it++) {
        const int i = i0 + it * 4;

        __syncthreads();
        // ---- stage 4 rows: coalesced LDG.128 -> padded smem rows ----
#pragma unroll
        for (int rr = 0; rr < 4; rr++) {
            const float4* src =
                reinterpret_cast<const float4*>(edges + ((size_t)(i + rr) * 1024 + j0) * 32);
            float* dstbase = s_in + rr * 128 * ROWPAD;
#pragma unroll
            for (int q = 0; q < 8; q++) {
                int g   = q * 128 + tid;
                int row = g >> 3;
                int kk  = g & 7;
                float4 v = src[g];
                *reinterpret_cast<float4*>(dstbase + row * ROWPAD + kk * 4) = v;
            }
        }
        __syncthreads();

        // ---- layer 1: 4 rows share every weight load ----
        u64 h2[4][8];
#pragma unroll
        for (int r = 0; r < 4; r++) {
#pragma unroll
            for (int p = 0; p < 8; p++) {
                float a0 = s_pa[(it * 4 + r) * 16 + 2 * p];       // uniform LDS
                float a1 = s_pa[(it * 4 + r) * 16 + 2 * p + 1];
                h2[r][p] = pack2(a0 + pb[2 * p], a1 + pb[2 * p + 1]);
            }
        }

#pragma unroll
        for (int u = 0; u < 8; u++) {
            float4 xr[4];
#pragma unroll
            for (int r = 0; r < 4; r++)
                xr[r] = *reinterpret_cast<const float4*>(s_in + r * 128 * ROWPAD + tid * ROWPAD + u * 4);
#pragma unroll
            for (int kk = 0; kk < 4; kk++) {
                const ulonglong2* w2 =
                    reinterpret_cast<const ulonglong2*>(cWe1p + (64 + u * 4 + kk) * 8);
                ulonglong2 wA = w2[0], wB = w2[1], wC = w2[2], wD = w2[3];
#pragma unroll
                for (int r = 0; r < 4; r++) {
                    const float xs = (kk == 0) ? xr[r].x : (kk == 1) ? xr[r].y
                                   : (kk == 2) ? xr[r].z : xr[r].w;
                    const u64 a = pack2(xs, xs);
                    h2[r][0] = ffma2(a, wA.x, h2[r][0]);
                    h2[r][1] = ffma2(a, wA.y, h2[r][1]);
                    h2[r][2] = ffma2(a, wB.x, h2[r][2]);
                    h2[r][3] = ffma2(a, wB.y, h2[r][3]);
                    h2[r][4] = ffma2(a, wC.x, h2[r][4]);
                    h2[r][5] = ffma2(a, wC.y, h2[r][5]);
                    h2[r][6] = ffma2(a, wD.x, h2[r][6]);
                    h2[r][7] = ffma2(a, wD.y, h2[r][7]);
                }
            }
        }

        // relu -> h floats (h2 dead after this)
        float h[4][16];
#pragma unroll
        for (int r = 0; r < 4; r++)
#pragma unroll
            for (int p = 0; p < 8; p++) {
                float lo, hi; unpack2(h2[r][p], lo, hi);
                h[r][2 * p]     = fmaxf(lo, 0.0f);
                h[r][2 * p + 1] = fmaxf(hi, 0.0f);
            }

        // ---- layer 2: process rows pairwise (weight load shared by 2 rows) ----
#pragma unroll
        for (int pr = 0; pr < 2; pr++) {
            const int ra = pr * 2, rb = pr * 2 + 1;
            u64 e2[2][8];
#pragma unroll
            for (int p = 0; p < 8; p++) { e2[0][p] = be2p[p]; e2[1][p] = be2p[p]; }
#pragma unroll
            for (int k = 0; k < 16; k++) {
                const u64 a0 = pack2(h[ra][k], h[ra][k]);
                const u64 a1 = pack2(h[rb][k], h[rb][k]);
                const ulonglong2* w2 = reinterpret_cast<const ulonglong2*>(cWe2p + k * 8);
                ulonglong2 wA = w2[0], wB = w2[1], wC = w2[2], wD = w2[3];
                e2[0][0] = ffma2(a0, wA.x, e2[0][0]); e2[0][1] = ffma2(a0, wA.y, e2[0][1]);
                e2[0][2] = ffma2(a0, wB.x, e2[0][2]); e2[0][3] = ffma2(a0, wB.y, e2[0][3]);
                e2[0][4] = ffma2(a0, wC.x, e2[0][4]); e2[0][5] = ffma2(a0, wC.y, e2[0][5]);
                e2[0][6] = ffma2(a0, wD.x, e2[0][6]); e2[0][7] = ffma2(a0, wD.y, e2[0][7]);
                e2[1][0] = ffma2(a1, wA.x, e2[1][0]); e2[1][1] = ffma2(a1, wA.y, e2[1][1]);
                e2[1][2] = ffma2(a1, wB.x, e2[1][2]); e2[1][3] = ffma2(a1, wB.y, e2[1][3]);
                e2[1][4] = ffma2(a1, wC.x, e2[1][4]); e2[1][5] = ffma2(a1, wC.y, e2[1][5]);
                e2[1][6] = ffma2(a1, wD.x, e2[1][6]); e2[1][7] = ffma2(a1, wD.y, e2[1][7]);
            }

#pragma unroll
            for (int rr = 0; rr < 2; rr++) {
                const int irow = i + pr * 2 + rr;
                float e[16];
#pragma unroll
                for (int p = 0; p < 8; p++) {
                    float lo, hi; unpack2(e2[rr][p], lo, hi);
                    e[2 * p]     = fmaxf(lo, 0.0f);
                    e[2 * p + 1] = fmaxf(hi, 0.0f);
                }

                float4* op = reinterpret_cast<float4*>(out_e + ((size_t)irow * 1024 + j) * 16);
#pragma unroll
                for (int q = 0; q < 4; q++)
                    op[q] = make_float4(e[4 * q], e[4 * q + 1], e[4 * q + 2], e[4 * q + 3]);

#pragma unroll
                for (int c = 0; c < 16; c++) msgb[c] += e[c];

                float total = warp_reduce16(e, lane);
                if (lane < 16) atomicAdd(&g_msga[irow * 16 + chan16(lane)], total);
            }
        }
    }

#pragma unroll
    for (int c = 0; c < 16; c++) atomicAdd(&g_msgb[j * 16 + c], msgb[c]);
}

// ============ Kernel C: node MLP (constant weights, uniform LDC) ============
__global__ __launch_bounds__(256) void node_kernel(const float* __restrict__ na,
                                                   const float* __restrict__ nb,
                                                   float* __restrict__ out_a,
                                                   float* __restrict__ out_b) {
    int r = blockIdx.x * blockDim.x + threadIdx.x;
    if (r >= 2 * N_NODES) return;

    const float* node;
    const float* msg;
    float* out;
    if (r < N_NODES) {
        node = na + r * 32;  msg = g_msga + r * 16;  out = out_a + r * 32;
    } else {
        int rr = r - N_NODES;
        node = nb + rr * 32; msg = g_msgb + rr * 16; out = out_b + rr * 32;
    }

    float x[48];
#pragma unroll
    for (int k = 0; k < 32; k++) x[k] = node[k];
#pragma unroll
    for (int k = 0; k < 16; k++) x[32 + k] = msg[k];

    float h[32];
#pragma unroll
    for (int c = 0; c < 32; c++) h[c] = cbn1[c];
#pragma unroll
    for (int k = 0; k < 48; k++) {
#pragma unroll
        for (int c = 0; c < 32; c++)
            h[c] = fmaf(x[k], cWn1[k * 32 + c], h[c]);
    }
#pragma unroll
    for (int c = 0; c < 32; c++) h[c] = fmaxf(h[c], 0.0f);

    float o[32];
#pragma unroll
    for (int c = 0; c < 32; c++) o[c] = cbn2[c];
#pragma unroll
    for (int k = 0; k < 32; k++) {
#pragma unroll
        for (int c = 0; c < 32; c++)
            o[c] = fmaf(h[k], cWn2[k * 32 + c], o[c]);
    }
#pragma unroll
    for (int c = 0; c < 32; c++) out[c] = fmaxf(o[c], 0.0f);
}

// ============ launch ============
extern "C" void kernel_launch(void* const* d_in, const int* in_sizes, int n_in,
                              void* d_out, int out_size) {
    const float* edges = (const float*)d_in[0];
    const float* na    = (const float*)d_in[1];
    const float* nb    = (const float*)d_in[2];
    const float* We1   = (const float*)d_in[3];
    const float* be1   = (const float*)d_in[4];

    cudaMemcpyToSymbolAsync(cWe1, d_in[3], 96 * 16 * sizeof(float), 0, cudaMemcpyDeviceToDevice);
    cudaMemcpyToSymbolAsync(cWe2, d_in[5], 16 * 16 * sizeof(float), 0, cudaMemcpyDeviceToDevice);
    cudaMemcpyToSymbolAsync(cbe2, d_in[6], 16 * sizeof(float),      0, cudaMemcpyDeviceToDevice);
    cudaMemcpyToSymbolAsync(cWn1, d_in[7], 48 * 32 * sizeof(float), 0, cudaMemcpyDeviceToDevice);
    cudaMemcpyToSymbolAsync(cbn1, d_in[8], 32 * sizeof(float),      0, cudaMemcpyDeviceToDevice);
    cudaMemcpyToSymbolAsync(cWn2, d_in[9], 32 * 32 * sizeof(float), 0, cudaMemcpyDeviceToDevice);
    cudaMemcpyToSymbolAsync(cbn2, d_in[10], 32 * sizeof(float),     0, cudaMemcpyDeviceToDevice);

    float* out_e = (float*)d_out;
    float* out_a = out_e + (size_t)1024 * 1024 * 16;
    float* out_b = out_a + 1024 * 32;

    prep_kernel<<<32, 256>>>(na, nb, We1, be1);

    static bool attr_set = false;
    if (!attr_set) {
        cudaFuncSetAttribute(edge_kernel, cudaFuncAttributeMaxDynamicSharedMemorySize,
                             EDGE_SMEM_BYTES);
        attr_set = true;
    }
    dim3 grid(8, 128);
    edge_kernel<<<grid, 128, EDGE_SMEM_BYTES>>>(edges, out_e);

    node_kernel<<<8, 256>>>(na, nb, out_a, out_b);
}